// round 14
// baseline (speedup 1.0000x reference)
#include <cuda_runtime.h>
#include <cuda_fp16.h>
#include <mma.h>
using namespace nvcuda;

#define N_NODES 100000
#define E_EDGES 1600000
#define D 128

#define GEMM_BLOCKS ((N_NODES + 127) / 128)     // 782  (128 rows/block)
#define HIST_BLOCKS (E_EDGES / 512)             // 3125 (512 edges/block)
#define K1_BLOCKS   (GEMM_BLOCKS + HIST_BLOCKS)

// ---------------- scratch (static device globals; no runtime alloc) ---------
__device__ __half g_feat_h[N_NODES * D];  // projected features fp16 (25.6 MB)
__device__ float  g_el[N_NODES];          // src attention logits (fp32-exact)
__device__ float  g_er[N_NODES];          // dst attention logits
__device__ int    g_cnt[N_NODES];         // in-degree histogram (zeroed by scanC)
__device__ int    g_off[N_NODES + 1];     // CSR offsets (off[N]=E)
__device__ int    g_cur[N_NODES];         // scatter cursors
__device__ int2   g_sedge[E_EDGES];       // CSR slot: {src, exp-weight bits}

#define SCAN_BS 512
#define NPART ((N_NODES + SCAN_BS - 1) / SCAN_BS)   // 196
__device__ int g_part[NPART];
__device__ int g_pbase[NPART];

__device__ __forceinline__ float2 h2tof2(unsigned int u) {
    __half2 h;
    *reinterpret_cast<unsigned int*>(&h) = u;
    return __half22float2(h);
}

// ---------------- K1 mega: wmma gemm (+fused el/er) | hist ------------------
__global__ void __launch_bounds__(256)
mega1_kernel(const float* __restrict__ h, const float* __restrict__ W,
             const float* __restrict__ attn_l, const float* __restrict__ attn_r,
             const int* __restrict__ dst) {
    const int bid = blockIdx.x;
    const int t = threadIdx.x;

    if (bid < GEMM_BLOCKS) {
        // ---- gemm role: 128x128x128 tile, fp16 HMMA, fp32 accumulate ----
        __shared__ __half sa[128 * 32];     // A tile [128][32]           8 KB
        __shared__ __half sb[32 * 128];     // B tile [32][128]           8 KB
        __shared__ float  sepi[8 * 256];    // per-warp 16x16 staging     8 KB
        __shared__ float  swl[D];           // W @ attn_l                 .5 KB
        __shared__ float  swr[D];           // W @ attn_r                 .5 KB

        const int row0 = bid * 128;
        const int w    = t >> 5;            // warp 0..7
        const int lane = t & 31;
        const int wm   = w >> 1;            // 0..3 (32-row strip)
        const int wn   = w & 1;             // 0..1 (64-col strip)

        // per-block wl/wr (redundant but cheap; W is L2-hot)
        {
            const int k = t & 127;
            const float* v = (t < 128) ? attn_l : attn_r;
            float s = 0.f;
            #pragma unroll 8
            for (int j = 0; j < D; j++)
                s = fmaf(__ldg(&W[k * D + j]), __ldg(&v[j]), s);
            if (t < 128) swl[k] = s; else swr[k] = s;
        }
        __syncthreads();

        wmma::fragment<wmma::accumulator, 16, 16, 16, float> fc[2][4];
        #pragma unroll
        for (int i = 0; i < 2; i++)
            #pragma unroll
            for (int j = 0; j < 4; j++)
                wmma::fill_fragment(fc[i][j], 0.0f);

        // fused el/er partials: thread covers rows p*32+(t>>3), cols cg*4..+4
        float sl[4] = {0.f, 0.f, 0.f, 0.f};
        float sr[4] = {0.f, 0.f, 0.f, 0.f};
        const int cg = t & 7;

        #pragma unroll
        for (int k0 = 0; k0 < 4; k0++) {    // K chunks of 32
            const float4 wl4 = reinterpret_cast<const float4*>(swl + k0 * 32)[cg];
            const float4 wr4 = reinterpret_cast<const float4*>(swr + k0 * 32)[cg];
            // load A: rows row0..row0+127, cols k0*32..+32 (fp32 -> fp16)
            #pragma unroll
            for (int p = 0; p < 4; p++) {
                const int r = p * 32 + (t >> 3);
                int grow = row0 + r;
                if (grow >= N_NODES) grow = 0;      // junk rows, stores guarded
                const float4 v = __ldg(reinterpret_cast<const float4*>(
                                           h + grow * D + k0 * 32) + cg);
                sl[p] = fmaf(v.x, wl4.x, fmaf(v.y, wl4.y,
                         fmaf(v.z, wl4.z, fmaf(v.w, wl4.w, sl[p]))));
                sr[p] = fmaf(v.x, wr4.x, fmaf(v.y, wr4.y,
                         fmaf(v.z, wr4.z, fmaf(v.w, wr4.w, sr[p]))));
                __half2* dp = reinterpret_cast<__half2*>(&sa[r * 32 + cg * 4]);
                dp[0] = __floats2half2_rn(v.x, v.y);
                dp[1] = __floats2half2_rn(v.z, v.w);
            }
            // load B: W rows k0*32..+32, all 128 cols (fp32 -> fp16)
            #pragma unroll
            for (int p = 0; p < 4; p++) {
                const int idx4 = p * 256 + t;       // 0..1023 float4s
                const int r  = idx4 >> 5;
                const int c4 = idx4 & 31;
                const float4 v = __ldg(reinterpret_cast<const float4*>(
                                           W + (k0 * 32 + r) * D) + c4);
                __half2* dp = reinterpret_cast<__half2*>(&sb[r * 128 + c4 * 4]);
                dp[0] = __floats2half2_rn(v.x, v.y);
                dp[1] = __floats2half2_rn(v.z, v.w);
            }
            __syncthreads();

            #pragma unroll
            for (int kk = 0; kk < 32; kk += 16) {
                wmma::fragment<wmma::matrix_a, 16, 16, 16, __half, wmma::row_major> fa0, fa1;
                wmma::load_matrix_sync(fa0, &sa[(wm * 32)      * 32 + kk], 32);
                wmma::load_matrix_sync(fa1, &sa[(wm * 32 + 16) * 32 + kk], 32);
                #pragma unroll
                for (int j = 0; j < 4; j++) {
                    wmma::fragment<wmma::matrix_b, 16, 16, 16, __half, wmma::row_major> fb;
                    wmma::load_matrix_sync(fb, &sb[kk * 128 + wn * 64 + j * 16], 128);
                    wmma::mma_sync(fc[0][j], fa0, fb, fc[0][j]);
                    wmma::mma_sync(fc[1][j], fa1, fb, fc[1][j]);
                }
            }
            __syncthreads();
        }

        // el/er: reduce 8 lanes per row, write fp32-exact logits
        #pragma unroll
        for (int p = 0; p < 4; p++) {
            float a = sl[p], b = sr[p];
            #pragma unroll
            for (int o = 4; o; o >>= 1) {
                a += __shfl_down_sync(0xffffffffu, a, o, 8);
                b += __shfl_down_sync(0xffffffffu, b, o, 8);
            }
            const int grow = row0 + p * 32 + (t >> 3);
            if (cg == 0 && grow < N_NODES) {
                g_el[grow] = a;
                g_er[grow] = b;
            }
        }

        // epilogue: per-warp 16x16 staging -> fp16 global (STG.128)
        float* ep = &sepi[w * 256];
        #pragma unroll
        for (int i = 0; i < 2; i++) {
            #pragma unroll
            for (int j = 0; j < 4; j++) {
                wmma::store_matrix_sync(ep, fc[i][j], 16, wmma::mem_row_major);
                __syncwarp();
                const int rr = lane >> 1;
                const int cc = (lane & 1) * 8;
                const int grow = row0 + wm * 32 + i * 16 + rr;
                if (grow < N_NODES) {
                    const float* sp = &ep[rr * 16 + cc];
                    __half2 q0 = __floats2half2_rn(sp[0], sp[1]);
                    __half2 q1 = __floats2half2_rn(sp[2], sp[3]);
                    __half2 q2 = __floats2half2_rn(sp[4], sp[5]);
                    __half2 q3 = __floats2half2_rn(sp[6], sp[7]);
                    uint4 pk;
                    pk.x = *reinterpret_cast<unsigned*>(&q0);
                    pk.y = *reinterpret_cast<unsigned*>(&q1);
                    pk.z = *reinterpret_cast<unsigned*>(&q2);
                    pk.w = *reinterpret_cast<unsigned*>(&q3);
                    *reinterpret_cast<uint4*>(
                        &g_feat_h[grow * D + wn * 64 + j * 16 + cc]) = pk;
                }
                __syncwarp();
            }
        }
    } else {
        // ---- hist role: 512 edges per block ----
        const int e0 = (bid - GEMM_BLOCKS) * 512 + t;
        atomicAdd(&g_cnt[dst[e0]], 1);
        atomicAdd(&g_cnt[dst[e0 + 256]], 1);
    }
}

// ---------------- K2: scanA (per-part reduction) ----------------------------
__global__ void __launch_bounds__(SCAN_BS)
scanA_kernel() {
    __shared__ int sh[SCAN_BS];
    const int t = threadIdx.x;
    const int i = blockIdx.x * SCAN_BS + t;
    sh[t] = (i < N_NODES) ? g_cnt[i] : 0;
    __syncthreads();
    #pragma unroll
    for (int o = SCAN_BS / 2; o; o >>= 1) {
        if (t < o) sh[t] += sh[t + o];
        __syncthreads();
    }
    if (t == 0) g_part[blockIdx.x] = sh[0];
}

// ---------------- K3: scanB (partial prefix) --------------------------------
__global__ void __launch_bounds__(256)
scanB_kernel() {
    __shared__ int sh[256];
    const int t = threadIdx.x;
    const int v = (t < NPART) ? g_part[t] : 0;
    sh[t] = v;
    __syncthreads();
    for (int o = 1; o < 256; o <<= 1) {
        const int x = (t >= o) ? sh[t - o] : 0;
        __syncthreads();
        sh[t] += x;
        __syncthreads();
    }
    if (t < NPART) g_pbase[t] = sh[t] - v;       // exclusive
}

// ---------------- K4: scanC (local scan + cursors + cnt reset) --------------
__global__ void __launch_bounds__(SCAN_BS)
scanC_kernel() {
    __shared__ int sh[SCAN_BS];
    const int t = threadIdx.x;
    const int i = blockIdx.x * SCAN_BS + t;
    const int c = (i < N_NODES) ? g_cnt[i] : 0;
    sh[t] = c;
    __syncthreads();
    for (int o = 1; o < SCAN_BS; o <<= 1) {
        const int x = (t >= o) ? sh[t - o] : 0;
        __syncthreads();
        sh[t] += x;
        __syncthreads();
    }
    if (i < N_NODES) {
        const int off = g_pbase[blockIdx.x] + sh[t] - c;   // exclusive
        g_off[i] = off;
        g_cur[i] = off;
        g_cnt[i] = 0;                       // restore invariant for next replay
    }
    if (blockIdx.x == 0 && t == 0) g_off[N_NODES] = E_EDGES;
}

// ---------------- K5: fused edge score + CSR scatter ------------------------
__global__ void __launch_bounds__(256)
scatter_kernel(const int* __restrict__ src, const int* __restrict__ dst) {
    const int e = blockIdx.x * blockDim.x + threadIdx.x;
    if (e >= E_EDGES) return;
    const int s = src[e];
    const int d = dst[e];
    float x = g_el[s] + g_er[d];
    x = (x > 0.f) ? x : 0.2f * x;            // leaky relu
    const float ex = __expf(x);              // |x| small: no max-shift needed
    const int idx = atomicAdd(&g_cur[d], 1);
    g_sedge[idx] = make_int2(s, __float_as_int(ex));
}

// ---------------- K6: aggregation — warp/node, lane-parallel edge fetch -----
__global__ void __launch_bounds__(256)
agg_kernel(float* __restrict__ out) {
    const int warp = (blockIdx.x * blockDim.x + threadIdx.x) >> 5;
    const int lane = threadIdx.x & 31;
    if (warp >= N_NODES) return;

    const int beg = g_off[warp];
    const int end = g_off[warp + 1];

    const uint2* __restrict__ featv = reinterpret_cast<const uint2*>(g_feat_h);

    float4 acc = make_float4(0.f, 0.f, 0.f, 0.f);
    float den = 0.f;

    for (int base = beg; base < end; base += 32) {
        const int n = min(32, end - base);
        int2 p = (lane < n) ? g_sedge[base + lane] : make_int2(0, 0);
        int c = 0;
        for (; c + 4 <= n; c += 4) {
            const int   s0 = __shfl_sync(0xffffffffu, p.x, c);
            const float w0 = __int_as_float(__shfl_sync(0xffffffffu, p.y, c));
            const int   s1 = __shfl_sync(0xffffffffu, p.x, c + 1);
            const float w1 = __int_as_float(__shfl_sync(0xffffffffu, p.y, c + 1));
            const int   s2 = __shfl_sync(0xffffffffu, p.x, c + 2);
            const float w2 = __int_as_float(__shfl_sync(0xffffffffu, p.y, c + 2));
            const int   s3 = __shfl_sync(0xffffffffu, p.x, c + 3);
            const float w3 = __int_as_float(__shfl_sync(0xffffffffu, p.y, c + 3));
            const uint2 v0 = __ldg(&featv[s0 * 32 + lane]);
            const uint2 v1 = __ldg(&featv[s1 * 32 + lane]);
            const uint2 v2 = __ldg(&featv[s2 * 32 + lane]);
            const uint2 v3 = __ldg(&featv[s3 * 32 + lane]);
            den += (w0 + w1) + (w2 + w3);
            const float2 a0 = h2tof2(v0.x), b0 = h2tof2(v0.y);
            const float2 a1 = h2tof2(v1.x), b1 = h2tof2(v1.y);
            const float2 a2 = h2tof2(v2.x), b2 = h2tof2(v2.y);
            const float2 a3 = h2tof2(v3.x), b3 = h2tof2(v3.y);
            acc.x = fmaf(w0, a0.x, acc.x); acc.y = fmaf(w0, a0.y, acc.y);
            acc.z = fmaf(w0, b0.x, acc.z); acc.w = fmaf(w0, b0.y, acc.w);
            acc.x = fmaf(w1, a1.x, acc.x); acc.y = fmaf(w1, a1.y, acc.y);
            acc.z = fmaf(w1, b1.x, acc.z); acc.w = fmaf(w1, b1.y, acc.w);
            acc.x = fmaf(w2, a2.x, acc.x); acc.y = fmaf(w2, a2.y, acc.y);
            acc.z = fmaf(w2, b2.x, acc.z); acc.w = fmaf(w2, b2.y, acc.w);
            acc.x = fmaf(w3, a3.x, acc.x); acc.y = fmaf(w3, a3.y, acc.y);
            acc.z = fmaf(w3, b3.x, acc.z); acc.w = fmaf(w3, b3.y, acc.w);
        }
        for (; c < n; c++) {
            const int   s = __shfl_sync(0xffffffffu, p.x, c);
            const float w = __int_as_float(__shfl_sync(0xffffffffu, p.y, c));
            const uint2 v = __ldg(&featv[s * 32 + lane]);
            den += w;
            const float2 a = h2tof2(v.x), b = h2tof2(v.y);
            acc.x = fmaf(w, a.x, acc.x); acc.y = fmaf(w, a.y, acc.y);
            acc.z = fmaf(w, b.x, acc.z); acc.w = fmaf(w, b.y, acc.w);
        }
    }
    const float inv = 1.f / fmaxf(den, 1e-9f);
    acc.x *= inv; acc.y *= inv; acc.z *= inv; acc.w *= inv;
    reinterpret_cast<float4*>(out)[warp * 32 + lane] = acc;
}

// ---------------- launch: 6 kernels, single stream --------------------------
extern "C" void kernel_launch(void* const* d_in, const int* in_sizes, int n_in,
                              void* d_out, int out_size) {
    const float* h      = (const float*)d_in[0];
    const int*   src    = (const int*)  d_in[1];
    const int*   dst    = (const int*)  d_in[2];
    const float* W      = (const float*)d_in[3];
    const float* attn_l = (const float*)d_in[4];
    const float* attn_r = (const float*)d_in[5];
    float* out = (float*)d_out;

    mega1_kernel  <<<K1_BLOCKS, 256>>>(h, W, attn_l, attn_r, dst);
    scanA_kernel  <<<NPART, SCAN_BS>>>();
    scanB_kernel  <<<1, 256>>>();
    scanC_kernel  <<<NPART, SCAN_BS>>>();
    scatter_kernel<<<(E_EDGES + 255) / 256, 256>>>(src, dst);
    agg_kernel    <<<(N_NODES * 32 + 255) / 256, 256>>>(out);
}

// round 17
// speedup vs baseline: 1.5598x; 1.5598x over previous
#include <cuda_runtime.h>
#include <cuda_fp16.h>
#include <mma.h>
using namespace nvcuda;

#define N_NODES 100000
#define E_EDGES 1600000
#define D 128

#define GEMM_BLOCKS ((N_NODES + 127) / 128)     // 782  (128 rows/block)
#define HIST_BLOCKS (E_EDGES / 512)             // 3125 (512 edges/block)
#define K1_BLOCKS   (GEMM_BLOCKS + HIST_BLOCKS)

// ---------------- scratch (static device globals; no runtime alloc) ---------
__device__ __half g_feat_h[N_NODES * D];  // projected features fp16 (25.6 MB)
__device__ float  g_el[N_NODES];          // src attention logits
__device__ float  g_er[N_NODES];          // dst attention logits
__device__ int    g_cnt[N_NODES];         // in-degree histogram (zeroed by scanC)
__device__ int    g_off[N_NODES + 1];     // CSR offsets (off[N]=E)
__device__ int    g_cur[N_NODES];         // scatter cursors
__device__ int2   g_sedge[E_EDGES];       // CSR slot: {src, exp-weight bits}

#define SCAN_BS 512
#define NPART ((N_NODES + SCAN_BS - 1) / SCAN_BS)   // 196
#define ELR_BLOCKS (N_NODES / 16)                   // 6250 (16 warps/block)
__device__ int g_part[NPART];
__device__ int g_pbase[NPART];

__device__ __forceinline__ float2 h2tof2(unsigned int u) {
    __half2 h;
    *reinterpret_cast<unsigned int*>(&h) = u;
    return __half22float2(h);
}

// ---------------- K1 mega: wmma gemm | hist by block range ------------------
__global__ void __launch_bounds__(256)
mega1_kernel(const float* __restrict__ h, const float* __restrict__ W,
             const int* __restrict__ dst) {
    const int bid = blockIdx.x;
    const int t = threadIdx.x;

    if (bid < GEMM_BLOCKS) {
        // ---- gemm role: 128x128x128 tile, fp16 HMMA, fp32 accumulate ----
        __shared__ __half sa[128 * 32];     // A tile [128][32]           8 KB
        __shared__ __half sb[32 * 128];     // B tile [32][128]           8 KB
        __shared__ float  sepi[8 * 256];    // per-warp 16x16 staging     8 KB

        const int row0 = bid * 128;
        const int w    = t >> 5;            // warp 0..7
        const int lane = t & 31;
        const int wm   = w >> 1;            // 0..3 (32-row strip)
        const int wn   = w & 1;             // 0..1 (64-col strip)

        wmma::fragment<wmma::accumulator, 16, 16, 16, float> fc[2][4];
        #pragma unroll
        for (int i = 0; i < 2; i++)
            #pragma unroll
            for (int j = 0; j < 4; j++)
                wmma::fill_fragment(fc[i][j], 0.0f);

        #pragma unroll
        for (int k0 = 0; k0 < 4; k0++) {    // K chunks of 32
            // load A: rows row0..row0+127, cols k0*32..+32 (fp32 -> fp16)
            #pragma unroll
            for (int p = 0; p < 4; p++) {
                const int r  = p * 32 + (t >> 3);
                const int cg = t & 7;
                int grow = row0 + r;
                if (grow >= N_NODES) grow = 0;      // junk rows, stores guarded
                const float4 v = __ldg(reinterpret_cast<const float4*>(
                                           h + grow * D + k0 * 32) + cg);
                __half2* dp = reinterpret_cast<__half2*>(&sa[r * 32 + cg * 4]);
                dp[0] = __floats2half2_rn(v.x, v.y);
                dp[1] = __floats2half2_rn(v.z, v.w);
            }
            // load B: W rows k0*32..+32, all 128 cols (fp32 -> fp16)
            #pragma unroll
            for (int p = 0; p < 4; p++) {
                const int idx4 = p * 256 + t;       // 0..1023 float4s
                const int r  = idx4 >> 5;
                const int cg = idx4 & 31;
                const float4 v = __ldg(reinterpret_cast<const float4*>(
                                           W + (k0 * 32 + r) * D) + cg);
                __half2* dp = reinterpret_cast<__half2*>(&sb[r * 128 + cg * 4]);
                dp[0] = __floats2half2_rn(v.x, v.y);
                dp[1] = __floats2half2_rn(v.z, v.w);
            }
            __syncthreads();

            #pragma unroll
            for (int kk = 0; kk < 32; kk += 16) {
                wmma::fragment<wmma::matrix_a, 16, 16, 16, __half, wmma::row_major> fa0, fa1;
                wmma::load_matrix_sync(fa0, &sa[(wm * 32)      * 32 + kk], 32);
                wmma::load_matrix_sync(fa1, &sa[(wm * 32 + 16) * 32 + kk], 32);
                #pragma unroll
                for (int j = 0; j < 4; j++) {
                    wmma::fragment<wmma::matrix_b, 16, 16, 16, __half, wmma::row_major> fb;
                    wmma::load_matrix_sync(fb, &sb[kk * 128 + wn * 64 + j * 16], 128);
                    wmma::mma_sync(fc[0][j], fa0, fb, fc[0][j]);
                    wmma::mma_sync(fc[1][j], fa1, fb, fc[1][j]);
                }
            }
            __syncthreads();
        }

        // epilogue: per-warp 16x16 staging -> fp16 global (STG.128)
        float* ep = &sepi[w * 256];
        #pragma unroll
        for (int i = 0; i < 2; i++) {
            #pragma unroll
            for (int j = 0; j < 4; j++) {
                wmma::store_matrix_sync(ep, fc[i][j], 16, wmma::mem_row_major);
                __syncwarp();
                const int rr = lane >> 1;
                const int cc = (lane & 1) * 8;
                const int grow = row0 + wm * 32 + i * 16 + rr;
                if (grow < N_NODES) {
                    const float* sp = &ep[rr * 16 + cc];
                    __half2 q0 = __floats2half2_rn(sp[0], sp[1]);
                    __half2 q1 = __floats2half2_rn(sp[2], sp[3]);
                    __half2 q2 = __floats2half2_rn(sp[4], sp[5]);
                    __half2 q3 = __floats2half2_rn(sp[6], sp[7]);
                    uint4 pk;
                    pk.x = *reinterpret_cast<unsigned*>(&q0);
                    pk.y = *reinterpret_cast<unsigned*>(&q1);
                    pk.z = *reinterpret_cast<unsigned*>(&q2);
                    pk.w = *reinterpret_cast<unsigned*>(&q3);
                    *reinterpret_cast<uint4*>(
                        &g_feat_h[grow * D + wn * 64 + j * 16 + cc]) = pk;
                }
                __syncwarp();
            }
        }
    } else {
        // ---- hist role: 512 edges per block ----
        const int e0 = (bid - GEMM_BLOCKS) * 512 + t;
        atomicAdd(&g_cnt[dst[e0]], 1);
        atomicAdd(&g_cnt[dst[e0 + 256]], 1);
    }
}

// ---------------- K2: scanA (per-part reduction) ----------------------------
__global__ void __launch_bounds__(SCAN_BS)
scanA_kernel() {
    __shared__ int sh[SCAN_BS];
    const int t = threadIdx.x;
    const int i = blockIdx.x * SCAN_BS + t;
    sh[t] = (i < N_NODES) ? g_cnt[i] : 0;
    __syncthreads();
    #pragma unroll
    for (int o = SCAN_BS / 2; o; o >>= 1) {
        if (t < o) sh[t] += sh[t + o];
        __syncthreads();
    }
    if (t == 0) g_part[blockIdx.x] = sh[0];
}

// ---------------- K3: scanB (partial prefix) --------------------------------
__global__ void __launch_bounds__(256)
scanB_kernel() {
    __shared__ int sh[256];
    const int t = threadIdx.x;
    const int v = (t < NPART) ? g_part[t] : 0;
    sh[t] = v;
    __syncthreads();
    for (int o = 1; o < 256; o <<= 1) {
        const int x = (t >= o) ? sh[t - o] : 0;
        __syncthreads();
        sh[t] += x;
        __syncthreads();
    }
    if (t < NPART) g_pbase[t] = sh[t] - v;       // exclusive
}

// ---------------- K4 merged: scanC | elr (fp16 feat) by block range ---------
// elr = feat . attn_{l,r}  (reference semantics; feat carries fp16 rounding)
__global__ void __launch_bounds__(SCAN_BS)
mega4_kernel(const float* __restrict__ attn_l, const float* __restrict__ attn_r) {
    const int bid = blockIdx.x;
    const int t = threadIdx.x;

    if (bid < NPART) {
        // ---- scanC role: local exclusive scan + cursor init + cnt reset ----
        __shared__ int sh[SCAN_BS];
        const int i = bid * SCAN_BS + t;
        const int c = (i < N_NODES) ? g_cnt[i] : 0;
        sh[t] = c;
        __syncthreads();
        for (int o = 1; o < SCAN_BS; o <<= 1) {
            const int x = (t >= o) ? sh[t - o] : 0;
            __syncthreads();
            sh[t] += x;
            __syncthreads();
        }
        if (i < N_NODES) {
            const int off = g_pbase[bid] + sh[t] - c;   // exclusive
            g_off[i] = off;
            g_cur[i] = off;
            g_cnt[i] = 0;                   // restore invariant for next replay
        }
        if (bid == 0 && t == 0) g_off[N_NODES] = E_EDGES;
    } else {
        // ---- elr role: warp per node, dot fp16 feat with attn_l/attn_r ----
        const int warp = (bid - NPART) * 16 + (t >> 5);
        const int lane = t & 31;
        if (warp >= N_NODES) return;

        const uint2 v = __ldg(&reinterpret_cast<const uint2*>(g_feat_h)[warp * 32 + lane]);
        const float2 a = h2tof2(v.x), b = h2tof2(v.y);
        const float4 al = __ldg(&reinterpret_cast<const float4*>(attn_l)[lane]);
        const float4 ar = __ldg(&reinterpret_cast<const float4*>(attn_r)[lane]);
        float sl = a.x * al.x + a.y * al.y + b.x * al.z + b.y * al.w;
        float sr = a.x * ar.x + a.y * ar.y + b.x * ar.z + b.y * ar.w;
        #pragma unroll
        for (int o = 16; o; o >>= 1) {
            sl += __shfl_down_sync(0xffffffffu, sl, o);
            sr += __shfl_down_sync(0xffffffffu, sr, o);
        }
        if (lane == 0) { g_el[warp] = sl; g_er[warp] = sr; }
    }
}

// ---------------- K5: fused edge score + CSR scatter ------------------------
__global__ void __launch_bounds__(256)
scatter_kernel(const int* __restrict__ src, const int* __restrict__ dst) {
    const int e = blockIdx.x * blockDim.x + threadIdx.x;
    if (e >= E_EDGES) return;
    const int s = src[e];
    const int d = dst[e];
    float x = g_el[s] + g_er[d];
    x = (x > 0.f) ? x : 0.2f * x;            // leaky relu
    const float ex = __expf(x);              // |x| small: no max-shift needed
    const int idx = atomicAdd(&g_cur[d], 1);
    g_sedge[idx] = make_int2(s, __float_as_int(ex));
}

// ---------------- K6: aggregation — warp/node, lane-parallel edge fetch -----
__global__ void __launch_bounds__(256)
agg_kernel(float* __restrict__ out) {
    const int warp = (blockIdx.x * blockDim.x + threadIdx.x) >> 5;
    const int lane = threadIdx.x & 31;
    if (warp >= N_NODES) return;

    const int beg = g_off[warp];
    const int end = g_off[warp + 1];

    const uint2* __restrict__ featv = reinterpret_cast<const uint2*>(g_feat_h);

    float4 acc = make_float4(0.f, 0.f, 0.f, 0.f);
    float den = 0.f;

    for (int base = beg; base < end; base += 32) {
        const int n = min(32, end - base);
        int2 p = (lane < n) ? g_sedge[base + lane] : make_int2(0, 0);
        int c = 0;
        for (; c + 4 <= n; c += 4) {
            const int   s0 = __shfl_sync(0xffffffffu, p.x, c);
            const float w0 = __int_as_float(__shfl_sync(0xffffffffu, p.y, c));
            const int   s1 = __shfl_sync(0xffffffffu, p.x, c + 1);
            const float w1 = __int_as_float(__shfl_sync(0xffffffffu, p.y, c + 1));
            const int   s2 = __shfl_sync(0xffffffffu, p.x, c + 2);
            const float w2 = __int_as_float(__shfl_sync(0xffffffffu, p.y, c + 2));
            const int   s3 = __shfl_sync(0xffffffffu, p.x, c + 3);
            const float w3 = __int_as_float(__shfl_sync(0xffffffffu, p.y, c + 3));
            const uint2 v0 = __ldg(&featv[s0 * 32 + lane]);
            const uint2 v1 = __ldg(&featv[s1 * 32 + lane]);
            const uint2 v2 = __ldg(&featv[s2 * 32 + lane]);
            const uint2 v3 = __ldg(&featv[s3 * 32 + lane]);
            den += (w0 + w1) + (w2 + w3);
            const float2 a0 = h2tof2(v0.x), b0 = h2tof2(v0.y);
            const float2 a1 = h2tof2(v1.x), b1 = h2tof2(v1.y);
            const float2 a2 = h2tof2(v2.x), b2 = h2tof2(v2.y);
            const float2 a3 = h2tof2(v3.x), b3 = h2tof2(v3.y);
            acc.x = fmaf(w0, a0.x, acc.x); acc.y = fmaf(w0, a0.y, acc.y);
            acc.z = fmaf(w0, b0.x, acc.z); acc.w = fmaf(w0, b0.y, acc.w);
            acc.x = fmaf(w1, a1.x, acc.x); acc.y = fmaf(w1, a1.y, acc.y);
            acc.z = fmaf(w1, b1.x, acc.z); acc.w = fmaf(w1, b1.y, acc.w);
            acc.x = fmaf(w2, a2.x, acc.x); acc.y = fmaf(w2, a2.y, acc.y);
            acc.z = fmaf(w2, b2.x, acc.z); acc.w = fmaf(w2, b2.y, acc.w);
            acc.x = fmaf(w3, a3.x, acc.x); acc.y = fmaf(w3, a3.y, acc.y);
            acc.z = fmaf(w3, b3.x, acc.z); acc.w = fmaf(w3, b3.y, acc.w);
        }
        for (; c < n; c++) {
            const int   s = __shfl_sync(0xffffffffu, p.x, c);
            const float w = __int_as_float(__shfl_sync(0xffffffffu, p.y, c));
            const uint2 v = __ldg(&featv[s * 32 + lane]);
            den += w;
            const float2 a = h2tof2(v.x), b = h2tof2(v.y);
            acc.x = fmaf(w, a.x, acc.x); acc.y = fmaf(w, a.y, acc.y);
            acc.z = fmaf(w, b.x, acc.z); acc.w = fmaf(w, b.y, acc.w);
        }
    }
    const float inv = 1.f / fmaxf(den, 1e-9f);
    acc.x *= inv; acc.y *= inv; acc.z *= inv; acc.w *= inv;
    reinterpret_cast<float4*>(out)[warp * 32 + lane] = acc;
}

// ---------------- launch: 6 kernels, single stream --------------------------
extern "C" void kernel_launch(void* const* d_in, const int* in_sizes, int n_in,
                              void* d_out, int out_size) {
    const float* h      = (const float*)d_in[0];
    const int*   src    = (const int*)  d_in[1];
    const int*   dst    = (const int*)  d_in[2];
    const float* W      = (const float*)d_in[3];
    const float* attn_l = (const float*)d_in[4];
    const float* attn_r = (const float*)d_in[5];
    float* out = (float*)d_out;

    mega1_kernel  <<<K1_BLOCKS, 256>>>(h, W, dst);
    scanA_kernel  <<<NPART, SCAN_BS>>>();
    scanB_kernel  <<<1, 256>>>();
    mega4_kernel  <<<NPART + ELR_BLOCKS, SCAN_BS>>>(attn_l, attn_r);
    scatter_kernel<<<(E_EDGES + 255) / 256, 256>>>(src, dst);
    agg_kernel    <<<(N_NODES * 32 + 255) / 256, 256>>>(out);
}